// round 5
// baseline (speedup 1.0000x reference)
#include <cuda_runtime.h>
#include <cuda_fp16.h>
#include <cstddef>
#include <cstdint>

// ---------------- problem constants ----------------
#define N_NODES 100000
#define N_EDGES 1600000
#define IN_CH   128
#define HID     64
#define OUTC    32

// ---------------- static device scratch (no allocation allowed) ----------------
// g_cnt is zero-initialized at module load and re-zeroed by cleanup_kernel each
// invocation (off the critical path), so count_kernel can start immediately.
__device__ int     g_cnt[N_NODES];
__device__ int     g_rowptr[N_NODES + 1];
__device__ int     g_cursor[N_NODES];
__device__ int     g_bsum[256];
__device__ int     g_col[N_EDGES];
__device__ float   g_dinv[N_NODES];
__device__ __half2 g_h0[(size_t)N_NODES * 32];   // x @ W1            (fp16)
__device__ __half2 g_h1[(size_t)N_NODES * 32];   // relu(agg(h0)+b1)  (fp16)
__device__ __half2 g_h2[(size_t)N_NODES * 32];   // h1 @ [W_mu|W_ls]  (fp16)
__device__ int     g_is64;

// ---------------- dtype detection: int64 vs int32 edge_index ----------------
// int64 little-endian with node ids < 2^31 -> every high 32-bit word is zero.
__global__ void detect_kernel(const unsigned int* __restrict__ words) {
    __shared__ int nz;
    if (threadIdx.x == 0) nz = 0;
    __syncthreads();
    for (int t = threadIdx.x; t < 4096; t += blockDim.x)
        if (words[2 * t + 1] != 0u) nz = 1;   // benign race
    __syncthreads();
    if (threadIdx.x == 0) g_is64 = nz ? 0 : 1;
}

// ---------------- count in-degree (dst), 4 edges per thread ----------------
__global__ void count_kernel(const void* __restrict__ ei, int E) {
    int base = (blockIdx.x * blockDim.x + threadIdx.x) * 4;
    if (base >= E) return;
    int n = E - base; if (n > 4) n = 4;
    if (g_is64) {
        const long long* d = (const long long*)ei + E;
        #pragma unroll
        for (int k = 0; k < 4; k++)
            if (k < n) atomicAdd(&g_cnt[(int)d[base + k]], 1);
    } else {
        const int* d = (const int*)ei + E;
        #pragma unroll
        for (int k = 0; k < 4; k++)
            if (k < n) atomicAdd(&g_cnt[d[base + k]], 1);
    }
}

// ---------------- scan stage 1: per-512-block exclusive scan ----------------
__global__ void scan1_kernel() {
    __shared__ int sh[512];
    int tid = threadIdx.x;
    int gid = blockIdx.x * 512 + tid;
    int v = (gid < N_NODES) ? g_cnt[gid] : 0;
    sh[tid] = v;
    __syncthreads();
    #pragma unroll
    for (int off = 1; off < 512; off <<= 1) {
        int t = (tid >= off) ? sh[tid - off] : 0;
        __syncthreads();
        sh[tid] += t;
        __syncthreads();
    }
    if (gid < N_NODES) g_rowptr[gid] = sh[tid] - v;  // exclusive within block
    if (tid == 511) g_bsum[blockIdx.x] = sh[511];
}

// ------- finalize (fused scan2): each block scans bsum redundantly in smem ----
__global__ void finalize_kernel(int E, int nb) {
    __shared__ int sh[256];
    __shared__ int ex[256];
    int tid = threadIdx.x;
    int v = (tid < nb) ? g_bsum[tid] : 0;
    sh[tid] = v;
    __syncthreads();
    #pragma unroll
    for (int off = 1; off < 256; off <<= 1) {
        int t = (tid >= off) ? sh[tid - off] : 0;
        __syncthreads();
        sh[tid] += t;
        __syncthreads();
    }
    ex[tid] = sh[tid] - v;  // exclusive block offsets
    __syncthreads();

    int i = blockIdx.x * 256 + tid;
    if (i < N_NODES) {
        int r = g_rowptr[i] + ex[i >> 9];
        g_rowptr[i] = r;
        g_cursor[i] = r;
        g_dinv[i] = rsqrtf((float)(g_cnt[i] + 1));  // +1 self loop
    }
    if (i == 0) g_rowptr[N_NODES] = E;
}

// ---------------- fill CSR column indices, 4 edges per thread ----------------
__global__ void fill_kernel(const void* __restrict__ ei, int E) {
    int base = (blockIdx.x * blockDim.x + threadIdx.x) * 4;
    if (base >= E) return;
    int n = E - base; if (n > 4) n = 4;
    if (g_is64) {
        const long long* s = (const long long*)ei;
        const long long* d = s + E;
        #pragma unroll
        for (int k = 0; k < 4; k++)
            if (k < n) {
                int pos = atomicAdd(&g_cursor[(int)d[base + k]], 1);
                g_col[pos] = (int)s[base + k];
            }
    } else {
        const int* s = (const int*)ei;
        const int* d = s + E;
        #pragma unroll
        for (int k = 0; k < 4; k++)
            if (k < n) {
                int pos = atomicAdd(&g_cursor[d[base + k]], 1);
                g_col[pos] = s[base + k];
            }
    }
}

// ------- cleanup: re-zero g_cnt for next invocation (runs off critical path) --
__global__ void cleanup_kernel() {
    int i = blockIdx.x * blockDim.x + threadIdx.x;
    if (i < N_NODES) g_cnt[i] = 0;
}

// ---------------- tf32 helper ----------------
__device__ __forceinline__ uint32_t f2tf32(float x) {
    uint32_t r;
    asm("cvt.rna.tf32.f32 %0, %1;" : "=r"(r) : "f"(x));
    return r;
}

// ---------------- TF32 tensor-core GEMM: out[N,64] = A[N,K] @ W[K,64] ----------
// A dtype templated (float for layer 1, __half for layer 2). Output fp16 (half2).
// If Wb != null, W[k][c] = c<32 ? Wa[k*32+c] : Wb[k*32+c-32].
// 8 warps; warp w: rows [blk*128+w*16, +16) x all 64 cols via 8 m16n8k8 tiles.
// W transposed in smem with row stride 132 -> conflict-free B-fragment LDS.
template <typename TA>
__global__ __launch_bounds__(256) void gemm_tf32_kernel(
        const TA* __restrict__ A,
        const float* __restrict__ Wa,
        const float* __restrict__ Wb,
        __half2* __restrict__ out,
        int N, int K) {
    __shared__ float WsT[64 * 132];
    const int tid = threadIdx.x;

    for (int e = tid; e < 64 * K; e += 256) {
        int c = e & 63;
        int k = e >> 6;
        float w;
        if (Wb) w = (c < 32) ? Wa[k * 32 + c] : Wb[k * 32 + (c - 32)];
        else    w = Wa[k * 64 + c];
        WsT[c * 132 + k] = __uint_as_float(f2tf32(w));
    }
    __syncthreads();

    const int lane = tid & 31;
    const int warp = tid >> 5;
    const int g   = lane >> 2;   // 0..7
    const int tig = lane & 3;    // 0..3

    const int row0 = blockIdx.x * 128 + warp * 16 + g;
    const int row1 = row0 + 8;
    const bool v0 = row0 < N;
    const bool v1 = row1 < N;
    const TA* A0 = A + (size_t)(v0 ? row0 : 0) * K;
    const TA* A1 = A + (size_t)(v1 ? row1 : 0) * K;

    float acc[8][4];
    #pragma unroll
    for (int i = 0; i < 8; i++)
        #pragma unroll
        for (int j = 0; j < 4; j++) acc[i][j] = 0.f;

    for (int kc = 0; kc < K; kc += 8) {
        uint32_t a0 = f2tf32(v0 ? (float)__ldg(A0 + kc + tig)     : 0.f);
        uint32_t a1 = f2tf32(v1 ? (float)__ldg(A1 + kc + tig)     : 0.f);
        uint32_t a2 = f2tf32(v0 ? (float)__ldg(A0 + kc + tig + 4) : 0.f);
        uint32_t a3 = f2tf32(v1 ? (float)__ldg(A1 + kc + tig + 4) : 0.f);
        #pragma unroll
        for (int nt = 0; nt < 8; nt++) {
            const float* bp = &WsT[(nt * 8 + g) * 132 + kc + tig];
            uint32_t b0 = __float_as_uint(bp[0]);
            uint32_t b1 = __float_as_uint(bp[4]);
            asm volatile(
                "mma.sync.aligned.m16n8k8.row.col.f32.tf32.tf32.f32 "
                "{%0,%1,%2,%3}, {%4,%5,%6,%7}, {%8,%9}, {%0,%1,%2,%3};"
                : "+f"(acc[nt][0]), "+f"(acc[nt][1]),
                  "+f"(acc[nt][2]), "+f"(acc[nt][3])
                : "r"(a0), "r"(a1), "r"(a2), "r"(a3), "r"(b0), "r"(b1));
        }
    }

    #pragma unroll
    for (int nt = 0; nt < 8; nt++) {
        int cp = nt * 4 + tig;   // half2 column-pair index (cols 2cp, 2cp+1)
        if (v0) out[(size_t)row0 * 32 + cp] = __floats2half2_rn(acc[nt][0], acc[nt][1]);
        if (v1) out[(size_t)row1 * 32 + cp] = __floats2half2_rn(acc[nt][2], acc[nt][3]);
    }
}

// ---------------- aggregation (gather over CSR): one warp per node ----------------
// out[d,:] = dinv[d]*sum_{s in nbrs(d)} dinv[s]*h[s,:] + dinv[d]^2*h[d,:] + bias
// h is fp16 (half2/lane = 128B/row = 1 L2 line). Accumulation in fp32.
// mode A (out_b == null): +bias_a, optional relu, write fp16 h-matrix out_a.
// mode B: split fp32 write — ch 0..31 (+bias_a) -> out_a, ch 32..63 (+bias_b) -> out_b.
__global__ void agg_kernel(const __half2* __restrict__ h,
                           const float* __restrict__ bias_a,
                           const float* __restrict__ bias_b,
                           void* __restrict__ out_a,
                           float* __restrict__ out_b,
                           int do_relu) {
    int warp = (blockIdx.x * blockDim.x + threadIdx.x) >> 5;
    int lane = threadIdx.x & 31;
    if (warp >= N_NODES) return;
    const int d = warp;

    int beg = g_rowptr[d];
    int end = g_rowptr[d + 1];
    float2 acc = make_float2(0.f, 0.f);

    int j = beg;
    for (; j + 3 < end; j += 4) {
        int s0 = g_col[j];
        int s1 = g_col[j + 1];
        int s2 = g_col[j + 2];
        int s3 = g_col[j + 3];
        float w0 = g_dinv[s0];
        float w1 = g_dinv[s1];
        float w2 = g_dinv[s2];
        float w3 = g_dinv[s3];
        float2 v0 = __half22float2(h[(size_t)s0 * 32 + lane]);
        float2 v1 = __half22float2(h[(size_t)s1 * 32 + lane]);
        float2 v2 = __half22float2(h[(size_t)s2 * 32 + lane]);
        float2 v3 = __half22float2(h[(size_t)s3 * 32 + lane]);
        acc.x = fmaf(w0, v0.x, acc.x);  acc.y = fmaf(w0, v0.y, acc.y);
        acc.x = fmaf(w1, v1.x, acc.x);  acc.y = fmaf(w1, v1.y, acc.y);
        acc.x = fmaf(w2, v2.x, acc.x);  acc.y = fmaf(w2, v2.y, acc.y);
        acc.x = fmaf(w3, v3.x, acc.x);  acc.y = fmaf(w3, v3.y, acc.y);
    }
    for (; j < end; j++) {
        int s0 = g_col[j];
        float w0 = g_dinv[s0];
        float2 v0 = __half22float2(h[(size_t)s0 * 32 + lane]);
        acc.x = fmaf(w0, v0.x, acc.x);
        acc.y = fmaf(w0, v0.y, acc.y);
    }

    float dd = g_dinv[d];
    float2 hs = __half22float2(h[(size_t)d * 32 + lane]);
    float sw = dd * dd;
    acc.x = fmaf(dd, acc.x, sw * hs.x);
    acc.y = fmaf(dd, acc.y, sw * hs.y);

    if (out_b == nullptr) {
        float2 b = ((const float2*)bias_a)[lane];
        acc.x += b.x; acc.y += b.y;
        if (do_relu) { acc.x = fmaxf(acc.x, 0.f); acc.y = fmaxf(acc.y, 0.f); }
        ((__half2*)out_a)[(size_t)d * 32 + lane] = __floats2half2_rn(acc.x, acc.y);
    } else {
        if (lane < 16) {
            float2 b = ((const float2*)bias_a)[lane];
            acc.x += b.x; acc.y += b.y;
            ((float2*)out_a)[(size_t)d * 16 + lane] = acc;
        } else {
            float2 b = ((const float2*)bias_b)[lane - 16];
            acc.x += b.x; acc.y += b.y;
            ((float2*)out_b)[(size_t)d * 16 + (lane - 16)] = acc;
        }
    }
}

// ---------------- stream/event context (created at program load) ----------------
namespace {
struct Ctx {
    cudaStream_t s2 = nullptr;
    cudaEvent_t e_fork = nullptr, e_g1 = nullptr, e_fin = nullptr, e_cl = nullptr;
    bool ok = false;
    Ctx() {
        ok = (cudaStreamCreateWithFlags(&s2, cudaStreamNonBlocking) == cudaSuccess) &&
             (cudaEventCreateWithFlags(&e_fork, cudaEventDisableTiming) == cudaSuccess) &&
             (cudaEventCreateWithFlags(&e_g1,   cudaEventDisableTiming) == cudaSuccess) &&
             (cudaEventCreateWithFlags(&e_fin,  cudaEventDisableTiming) == cudaSuccess) &&
             (cudaEventCreateWithFlags(&e_cl,   cudaEventDisableTiming) == cudaSuccess);
    }
};
Ctx g_ctx;
}

// ---------------- launch ----------------
extern "C" void kernel_launch(void* const* d_in, const int* in_sizes, int n_in,
                              void* d_out, int out_size) {
    const float* x    = (const float*)d_in[0];
    const void*  ei   = d_in[1];
    const float* W1   = (const float*)d_in[2];
    const float* b1   = (const float*)d_in[3];
    const float* W_mu = (const float*)d_in[4];
    const float* b_mu = (const float*)d_in[5];
    const float* W_ls = (const float*)d_in[6];
    const float* b_ls = (const float*)d_in[7];
    float* out = (float*)d_out;

    const int E = in_sizes[1] / 2;
    const int N = N_NODES;

    __half2* h0;  cudaGetSymbolAddress((void**)&h0, g_h0);
    __half2* h1;  cudaGetSymbolAddress((void**)&h1, g_h1);
    __half2* h2;  cudaGetSymbolAddress((void**)&h2, g_h2);

    const int eb4 = (E / 4 + 255) / 256 + 1;     // 4 edges/thread
    const int nb512 = (N + 511) / 512;           // 196

    const bool fork = g_ctx.ok;
    cudaStream_t s2 = fork ? g_ctx.s2 : (cudaStream_t)0;

    if (fork) {
        cudaEventRecord(g_ctx.e_fork, 0);
        cudaStreamWaitEvent(g_ctx.s2, g_ctx.e_fork, 0);
    }

    // ---- side stream: layer-1 GEMM (independent of CSR) ----
    gemm_tf32_kernel<float><<<(N + 127) / 128, 256, 0, s2>>>(x, W1, nullptr, h0, N, IN_CH);
    if (fork) cudaEventRecord(g_ctx.e_g1, g_ctx.s2);

    // ---- default stream: CSR build (g_cnt arrives pre-zeroed) ----
    detect_kernel<<<1, 256>>>((const unsigned int*)ei);
    count_kernel<<<eb4, 256>>>(ei, E);
    scan1_kernel<<<nb512, 512>>>();
    finalize_kernel<<<(N + 255) / 256, 256>>>(E, nb512);
    if (fork) cudaEventRecord(g_ctx.e_fin, 0);
    fill_kernel<<<eb4, 256>>>(ei, E);

    // ---- side stream: re-zero g_cnt, overlapped with the agg chain ----
    if (fork) {
        cudaStreamWaitEvent(g_ctx.s2, g_ctx.e_fin, 0);
        cleanup_kernel<<<(N + 255) / 256, 256, 0, g_ctx.s2>>>();
        cudaEventRecord(g_ctx.e_cl, g_ctx.s2);
    }

    // ---- layer 1 aggregate (+bias+relu), fp16 out ----
    if (fork) cudaStreamWaitEvent((cudaStream_t)0, g_ctx.e_g1, 0);
    agg_kernel<<<(N * 32 + 255) / 256, 256>>>(h0, b1, nullptr, h1, nullptr, 1);

    // ---- layer 2 fused mu|logstd GEMM ----
    gemm_tf32_kernel<__half><<<(N + 127) / 128, 256>>>((const __half*)h1, W_mu, W_ls, h2, N, HID);

    // ---- final aggregate, split fp32 writes to d_out ----
    if (fork) cudaStreamWaitEvent((cudaStream_t)0, g_ctx.e_cl, 0);
    agg_kernel<<<(N * 32 + 255) / 256, 256>>>(h2, b_mu, b_ls,
                                              out, out + (size_t)N * OUTC, 0);

    if (!fork) cleanup_kernel<<<(N + 255) / 256, 256>>>();
}

// round 6
// speedup vs baseline: 1.0059x; 1.0059x over previous
#include <cuda_runtime.h>
#include <cuda_fp16.h>
#include <cstddef>
#include <cstdint>

// ---------------- problem constants ----------------
#define N_NODES 100000
#define N_EDGES 1600000
#define IN_CH   128
#define HID     64
#define OUTC    32

// ---------------- static device scratch (no allocation allowed) ----------------
__device__ int     g_cnt[N_NODES];
__device__ int     g_rowptr[N_NODES + 1];
__device__ int     g_cursor[N_NODES];
__device__ int     g_bsum[256];
__device__ int     g_col[N_EDGES];
__device__ float   g_dinv[N_NODES];
__device__ __half2 g_h0[(size_t)N_NODES * 32];   // x @ W1            (fp16)
__device__ __half2 g_h1[(size_t)N_NODES * 32];   // relu(agg(h0)+b1)  (fp16)
__device__ __half2 g_h2[(size_t)N_NODES * 32];   // h1 @ [W_mu|W_ls]  (fp16)
__device__ int     g_is64;

// ---------------- zero counters + dtype detection (fused, R3-style) ----------
// int64 little-endian with node ids < 2^31 -> every high 32-bit word is zero.
__global__ void zero_detect_kernel(const unsigned int* __restrict__ words) {
    int i = blockIdx.x * blockDim.x + threadIdx.x;
    if (i < N_NODES) g_cnt[i] = 0;
    if (blockIdx.x == gridDim.x - 1) {
        __shared__ int nz;
        if (threadIdx.x == 0) nz = 0;
        __syncthreads();
        for (int t = threadIdx.x; t < 4096; t += blockDim.x)
            if (words[2 * t + 1] != 0u) nz = 1;   // benign race
        __syncthreads();
        if (threadIdx.x == 0) g_is64 = nz ? 0 : 1;
    }
}

// ---------------- count in-degree (dst), 1 edge per thread (R3-style) --------
__global__ void count_kernel(const void* __restrict__ ei, int E) {
    int e = blockIdx.x * blockDim.x + threadIdx.x;
    if (e >= E) return;
    int d;
    if (g_is64) d = (int)((const long long*)ei)[E + e];
    else        d = ((const int*)ei)[E + e];
    atomicAdd(&g_cnt[d], 1);
}

// ---------------- scan stage 1: per-512-block exclusive scan ----------------
__global__ void scan1_kernel() {
    __shared__ int sh[512];
    int tid = threadIdx.x;
    int gid = blockIdx.x * 512 + tid;
    int v = (gid < N_NODES) ? g_cnt[gid] : 0;
    sh[tid] = v;
    __syncthreads();
    #pragma unroll
    for (int off = 1; off < 512; off <<= 1) {
        int t = (tid >= off) ? sh[tid - off] : 0;
        __syncthreads();
        sh[tid] += t;
        __syncthreads();
    }
    if (gid < N_NODES) g_rowptr[gid] = sh[tid] - v;  // exclusive within block
    if (tid == 511) g_bsum[blockIdx.x] = sh[511];
}

// ------- finalize (fused scan2): each block re-scans bsum in smem ------------
__global__ void finalize_kernel(int E, int nb) {
    __shared__ int sh[256];
    __shared__ int ex[256];
    int tid = threadIdx.x;
    int v = (tid < nb) ? g_bsum[tid] : 0;
    sh[tid] = v;
    __syncthreads();
    #pragma unroll
    for (int off = 1; off < 256; off <<= 1) {
        int t = (tid >= off) ? sh[tid - off] : 0;
        __syncthreads();
        sh[tid] += t;
        __syncthreads();
    }
    ex[tid] = sh[tid] - v;  // exclusive block offsets
    __syncthreads();

    int i = blockIdx.x * 256 + tid;
    if (i < N_NODES) {
        int r = g_rowptr[i] + ex[i >> 9];
        g_rowptr[i] = r;
        g_cursor[i] = r;
        g_dinv[i] = rsqrtf((float)(g_cnt[i] + 1));  // +1 self loop
    }
    if (i == 0) g_rowptr[N_NODES] = E;
}

// ---------------- fill CSR column indices, 1 edge per thread ----------------
__global__ void fill_kernel(const void* __restrict__ ei, int E) {
    int e = blockIdx.x * blockDim.x + threadIdx.x;
    if (e >= E) return;
    int s, d;
    if (g_is64) {
        s = (int)((const long long*)ei)[e];
        d = (int)((const long long*)ei)[E + e];
    } else {
        s = ((const int*)ei)[e];
        d = ((const int*)ei)[E + e];
    }
    int pos = atomicAdd(&g_cursor[d], 1);
    g_col[pos] = s;
}

// ---------------- tf32 helper ----------------
__device__ __forceinline__ uint32_t f2tf32(float x) {
    uint32_t r;
    asm("cvt.rna.tf32.f32 %0, %1;" : "=r"(r) : "f"(x));
    return r;
}

// ---------------- TF32 tensor-core GEMM: out[N,64] = A[N,K] @ W[K,64] ----------
// A dtype templated (float for layer 1, __half for layer 2). Output fp16 half2.
// If Wb != null, W[k][c] = c<32 ? Wa[k*32+c] : Wb[k*32+c-32].
// 8 warps; warp w: rows [blk*128+w*16, +16) x all 64 cols via 8 m16n8k8 tiles.
// W transposed in smem with row stride 132 -> conflict-free B-fragment LDS.
template <typename TA>
__global__ __launch_bounds__(256) void gemm_tf32_kernel(
        const TA* __restrict__ A,
        const float* __restrict__ Wa,
        const float* __restrict__ Wb,
        __half2* __restrict__ out,
        int N, int K) {
    __shared__ float WsT[64 * 132];
    const int tid = threadIdx.x;

    for (int e = tid; e < 64 * K; e += 256) {
        int c = e & 63;
        int k = e >> 6;
        float w;
        if (Wb) w = (c < 32) ? Wa[k * 32 + c] : Wb[k * 32 + (c - 32)];
        else    w = Wa[k * 64 + c];
        WsT[c * 132 + k] = __uint_as_float(f2tf32(w));
    }
    __syncthreads();

    const int lane = tid & 31;
    const int warp = tid >> 5;
    const int g   = lane >> 2;   // 0..7
    const int tig = lane & 3;    // 0..3

    const int row0 = blockIdx.x * 128 + warp * 16 + g;
    const int row1 = row0 + 8;
    const bool v0 = row0 < N;
    const bool v1 = row1 < N;
    const TA* A0 = A + (size_t)(v0 ? row0 : 0) * K;
    const TA* A1 = A + (size_t)(v1 ? row1 : 0) * K;

    float acc[8][4];
    #pragma unroll
    for (int i = 0; i < 8; i++)
        #pragma unroll
        for (int j = 0; j < 4; j++) acc[i][j] = 0.f;

    for (int kc = 0; kc < K; kc += 8) {
        uint32_t a0 = f2tf32(v0 ? (float)__ldg(A0 + kc + tig)     : 0.f);
        uint32_t a1 = f2tf32(v1 ? (float)__ldg(A1 + kc + tig)     : 0.f);
        uint32_t a2 = f2tf32(v0 ? (float)__ldg(A0 + kc + tig + 4) : 0.f);
        uint32_t a3 = f2tf32(v1 ? (float)__ldg(A1 + kc + tig + 4) : 0.f);
        #pragma unroll
        for (int nt = 0; nt < 8; nt++) {
            const float* bp = &WsT[(nt * 8 + g) * 132 + kc + tig];
            uint32_t b0 = __float_as_uint(bp[0]);
            uint32_t b1 = __float_as_uint(bp[4]);
            asm volatile(
                "mma.sync.aligned.m16n8k8.row.col.f32.tf32.tf32.f32 "
                "{%0,%1,%2,%3}, {%4,%5,%6,%7}, {%8,%9}, {%0,%1,%2,%3};"
                : "+f"(acc[nt][0]), "+f"(acc[nt][1]),
                  "+f"(acc[nt][2]), "+f"(acc[nt][3])
                : "r"(a0), "r"(a1), "r"(a2), "r"(a3), "r"(b0), "r"(b1));
        }
    }

    #pragma unroll
    for (int nt = 0; nt < 8; nt++) {
        int cp = nt * 4 + tig;   // half2 column-pair index (cols 2cp, 2cp+1)
        if (v0) out[(size_t)row0 * 32 + cp] = __floats2half2_rn(acc[nt][0], acc[nt][1]);
        if (v1) out[(size_t)row1 * 32 + cp] = __floats2half2_rn(acc[nt][2], acc[nt][3]);
    }
}

// ---------------- aggregation (gather over CSR): one warp per node ----------------
// out[d,:] = dinv[d]*sum_{s in nbrs(d)} dinv[s]*h[s,:] + dinv[d]^2*h[d,:] + bias
// h is fp16: half2 per lane -> 128B per row = one L2 line per gather.
// mode A (out_b == null): +bias_a, optional relu, fp16 write to out_a.
// mode B: split fp32 — ch 0..31 (+bias_a) -> out_a, ch 32..63 (+bias_b) -> out_b.
__global__ void agg_kernel(const __half2* __restrict__ h,
                           const float* __restrict__ bias_a,
                           const float* __restrict__ bias_b,
                           void* __restrict__ out_a,
                           float* __restrict__ out_b,
                           int do_relu) {
    int warp = (blockIdx.x * blockDim.x + threadIdx.x) >> 5;
    int lane = threadIdx.x & 31;
    if (warp >= N_NODES) return;
    const int d = warp;

    int beg = g_rowptr[d];
    int end = g_rowptr[d + 1];
    float2 acc = make_float2(0.f, 0.f);

    int j = beg;
    for (; j + 3 < end; j += 4) {
        int s0 = g_col[j];
        int s1 = g_col[j + 1];
        int s2 = g_col[j + 2];
        int s3 = g_col[j + 3];
        float w0 = g_dinv[s0];
        float w1 = g_dinv[s1];
        float w2 = g_dinv[s2];
        float w3 = g_dinv[s3];
        float2 v0 = __half22float2(h[(size_t)s0 * 32 + lane]);
        float2 v1 = __half22float2(h[(size_t)s1 * 32 + lane]);
        float2 v2 = __half22float2(h[(size_t)s2 * 32 + lane]);
        float2 v3 = __half22float2(h[(size_t)s3 * 32 + lane]);
        acc.x = fmaf(w0, v0.x, acc.x);  acc.y = fmaf(w0, v0.y, acc.y);
        acc.x = fmaf(w1, v1.x, acc.x);  acc.y = fmaf(w1, v1.y, acc.y);
        acc.x = fmaf(w2, v2.x, acc.x);  acc.y = fmaf(w2, v2.y, acc.y);
        acc.x = fmaf(w3, v3.x, acc.x);  acc.y = fmaf(w3, v3.y, acc.y);
    }
    for (; j < end; j++) {
        int s0 = g_col[j];
        float w0 = g_dinv[s0];
        float2 v0 = __half22float2(h[(size_t)s0 * 32 + lane]);
        acc.x = fmaf(w0, v0.x, acc.x);
        acc.y = fmaf(w0, v0.y, acc.y);
    }

    float dd = g_dinv[d];
    float2 hs = __half22float2(h[(size_t)d * 32 + lane]);
    float sw = dd * dd;
    acc.x = fmaf(dd, acc.x, sw * hs.x);
    acc.y = fmaf(dd, acc.y, sw * hs.y);

    if (out_b == nullptr) {
        float2 b = ((const float2*)bias_a)[lane];
        acc.x += b.x; acc.y += b.y;
        if (do_relu) { acc.x = fmaxf(acc.x, 0.f); acc.y = fmaxf(acc.y, 0.f); }
        ((__half2*)out_a)[(size_t)d * 32 + lane] = __floats2half2_rn(acc.x, acc.y);
    } else {
        if (lane < 16) {
            float2 b = ((const float2*)bias_a)[lane];
            acc.x += b.x; acc.y += b.y;
            ((float2*)out_a)[(size_t)d * 16 + lane] = acc;
        } else {
            float2 b = ((const float2*)bias_b)[lane - 16];
            acc.x += b.x; acc.y += b.y;
            ((float2*)out_b)[(size_t)d * 16 + (lane - 16)] = acc;
        }
    }
}

// ---------------- stream/event context (created at program load) ----------------
namespace {
struct Ctx {
    cudaStream_t s2 = nullptr;
    cudaEvent_t e_fork = nullptr, e_join = nullptr;
    bool ok = false;
    Ctx() {
        ok = (cudaStreamCreateWithFlags(&s2, cudaStreamNonBlocking) == cudaSuccess) &&
             (cudaEventCreateWithFlags(&e_fork, cudaEventDisableTiming) == cudaSuccess) &&
             (cudaEventCreateWithFlags(&e_join, cudaEventDisableTiming) == cudaSuccess);
    }
};
Ctx g_ctx;
}

// ---------------- launch (R3 structure) ----------------
extern "C" void kernel_launch(void* const* d_in, const int* in_sizes, int n_in,
                              void* d_out, int out_size) {
    const float* x    = (const float*)d_in[0];
    const void*  ei   = d_in[1];
    const float* W1   = (const float*)d_in[2];
    const float* b1   = (const float*)d_in[3];
    const float* W_mu = (const float*)d_in[4];
    const float* b_mu = (const float*)d_in[5];
    const float* W_ls = (const float*)d_in[6];
    const float* b_ls = (const float*)d_in[7];
    float* out = (float*)d_out;

    const int E = in_sizes[1] / 2;
    const int N = N_NODES;

    __half2* h0;  cudaGetSymbolAddress((void**)&h0, g_h0);
    __half2* h1;  cudaGetSymbolAddress((void**)&h1, g_h1);
    __half2* h2;  cudaGetSymbolAddress((void**)&h2, g_h2);

    const int eb = (E + 255) / 256;
    const int nb512 = (N + 511) / 512;           // 196

    const bool fork = g_ctx.ok;
    cudaStream_t sc = fork ? g_ctx.s2 : (cudaStream_t)0;

    if (fork) {
        cudaEventRecord(g_ctx.e_fork, 0);
        cudaStreamWaitEvent(g_ctx.s2, g_ctx.e_fork, 0);
    }

    // ---- CSR build (side stream, overlaps gemm1) ----
    zero_detect_kernel<<<(N + 255) / 256 + 1, 256, 0, sc>>>((const unsigned int*)ei);
    count_kernel<<<eb, 256, 0, sc>>>(ei, E);
    scan1_kernel<<<nb512, 512, 0, sc>>>();
    finalize_kernel<<<(N + 255) / 256, 256, 0, sc>>>(E, nb512);
    fill_kernel<<<eb, 256, 0, sc>>>(ei, E);
    if (fork) cudaEventRecord(g_ctx.e_join, g_ctx.s2);

    // ---- layer 1 GEMM (default stream, independent of CSR) ----
    gemm_tf32_kernel<float><<<(N + 127) / 128, 256>>>(x, W1, nullptr, h0, N, IN_CH);

    if (fork) cudaStreamWaitEvent((cudaStream_t)0, g_ctx.e_join, 0);

    // ---- layer 1 aggregate (+bias+relu), fp16 out ----
    agg_kernel<<<(N * 32 + 255) / 256, 256>>>(h0, b1, nullptr, h1, nullptr, 1);

    // ---- layer 2 fused mu|logstd GEMM (fp16 A) ----
    gemm_tf32_kernel<__half><<<(N + 127) / 128, 256>>>((const __half*)h1, W_mu, W_ls, h2, N, HID);

    // ---- final aggregate, split fp32 writes to d_out ----
    agg_kernel<<<(N * 32 + 255) / 256, 256>>>(h2, b_mu, b_ls,
                                              out, out + (size_t)N * OUTC, 0);
}

// round 7
// speedup vs baseline: 1.0395x; 1.0334x over previous
#include <cuda_runtime.h>
#include <cuda_fp16.h>
#include <cstddef>
#include <cstdint>

// ---------------- problem constants ----------------
#define N_NODES 100000
#define N_EDGES 1600000
#define IN_CH   128
#define HID     64
#define OUTC    32

// ---------------- static device scratch (no allocation allowed) ----------------
__device__ int     g_cnt[N_NODES];
__device__ int     g_rowptr[N_NODES + 1];
__device__ int     g_cursor[N_NODES];
__device__ int     g_bsum[256];
__device__ __align__(16) int g_col[N_EDGES];
__device__ float   g_dinv[N_NODES];
__device__ __half2 g_h0[(size_t)N_NODES * 32];   // x @ W1, then pre-scaled by dinv
__device__ __half2 g_h1[(size_t)N_NODES * 32];   // dinv * relu(agg(h0s)+b1)
__device__ __half2 g_h2[(size_t)N_NODES * 32];   // h1s @ [W_mu|W_ls]  (pre-scaled)
__device__ int     g_is64;

// ---------------- zero counters + dtype detection (fused) --------------------
// int64 little-endian with node ids < 2^31 -> every high 32-bit word is zero.
__global__ void zero_detect_kernel(const unsigned int* __restrict__ words) {
    int i = blockIdx.x * blockDim.x + threadIdx.x;
    if (i < N_NODES) g_cnt[i] = 0;
    if (blockIdx.x == gridDim.x - 1) {
        __shared__ int nz;
        if (threadIdx.x == 0) nz = 0;
        __syncthreads();
        for (int t = threadIdx.x; t < 4096; t += blockDim.x)
            if (words[2 * t + 1] != 0u) nz = 1;   // benign race
        __syncthreads();
        if (threadIdx.x == 0) g_is64 = nz ? 0 : 1;
    }
}

// ---------------- count in-degree (dst), 1 edge per thread -------------------
__global__ void count_kernel(const void* __restrict__ ei, int E) {
    int e = blockIdx.x * blockDim.x + threadIdx.x;
    if (e >= E) return;
    int d;
    if (g_is64) d = (int)((const long long*)ei)[E + e];
    else        d = ((const int*)ei)[E + e];
    atomicAdd(&g_cnt[d], 1);
}

// ---------------- scan stage 1: per-512-block exclusive scan ----------------
__global__ void scan1_kernel() {
    __shared__ int sh[512];
    int tid = threadIdx.x;
    int gid = blockIdx.x * 512 + tid;
    int v = (gid < N_NODES) ? g_cnt[gid] : 0;
    sh[tid] = v;
    __syncthreads();
    #pragma unroll
    for (int off = 1; off < 512; off <<= 1) {
        int t = (tid >= off) ? sh[tid - off] : 0;
        __syncthreads();
        sh[tid] += t;
        __syncthreads();
    }
    if (gid < N_NODES) g_rowptr[gid] = sh[tid] - v;  // exclusive within block
    if (tid == 511) g_bsum[blockIdx.x] = sh[511];
}

// ------- finalize (fused scan2): each block re-scans bsum in smem ------------
__global__ void finalize_kernel(int E, int nb) {
    __shared__ int sh[256];
    __shared__ int ex[256];
    int tid = threadIdx.x;
    int v = (tid < nb) ? g_bsum[tid] : 0;
    sh[tid] = v;
    __syncthreads();
    #pragma unroll
    for (int off = 1; off < 256; off <<= 1) {
        int t = (tid >= off) ? sh[tid - off] : 0;
        __syncthreads();
        sh[tid] += t;
        __syncthreads();
    }
    ex[tid] = sh[tid] - v;  // exclusive block offsets
    __syncthreads();

    int i = blockIdx.x * 256 + tid;
    if (i < N_NODES) {
        int r = g_rowptr[i] + ex[i >> 9];
        g_rowptr[i] = r;
        g_cursor[i] = r;
        g_dinv[i] = rsqrtf((float)(g_cnt[i] + 1));  // +1 self loop
    }
    if (i == 0) g_rowptr[N_NODES] = E;
}

// ---------------- fill CSR column indices, 1 edge per thread ----------------
__global__ void fill_kernel(const void* __restrict__ ei, int E) {
    int e = blockIdx.x * blockDim.x + threadIdx.x;
    if (e >= E) return;
    int s, d;
    if (g_is64) {
        s = (int)((const long long*)ei)[e];
        d = (int)((const long long*)ei)[E + e];
    } else {
        s = ((const int*)ei)[e];
        d = ((const int*)ei)[E + e];
    }
    int pos = atomicAdd(&g_cursor[d], 1);
    g_col[pos] = s;
}

// ------- in-place pre-scale: h[i] *= dinv[node(i)] (node = i>>5) -------------
__global__ void scale_h_kernel(__half2* __restrict__ h) {
    int i = blockIdx.x * blockDim.x + threadIdx.x;
    if (i >= N_NODES * 32) return;
    float dd = g_dinv[i >> 5];
    float2 v = __half22float2(h[i]);
    h[i] = __floats2half2_rn(v.x * dd, v.y * dd);
}

// ---------------- tf32 helper ----------------
__device__ __forceinline__ uint32_t f2tf32(float x) {
    uint32_t r;
    asm("cvt.rna.tf32.f32 %0, %1;" : "=r"(r) : "f"(x));
    return r;
}

// ---------------- TF32 tensor-core GEMM: out[N,64] = A[N,K] @ W[K,64] ----------
// A dtype templated (float layer 1, __half layer 2). Output fp16 half2.
// If Wb != null, W[k][c] = c<32 ? Wa[k*32+c] : Wb[k*32+c-32].
// 8 warps; warp w: rows [blk*128+w*16, +16) x 64 cols via 8 m16n8k8 tiles.
// W transposed in smem, row stride 132 -> conflict-free B-fragment LDS.
template <typename TA>
__global__ __launch_bounds__(256) void gemm_tf32_kernel(
        const TA* __restrict__ A,
        const float* __restrict__ Wa,
        const float* __restrict__ Wb,
        __half2* __restrict__ out,
        int N, int K) {
    __shared__ float WsT[64 * 132];
    const int tid = threadIdx.x;

    for (int e = tid; e < 64 * K; e += 256) {
        int c = e & 63;
        int k = e >> 6;
        float w;
        if (Wb) w = (c < 32) ? Wa[k * 32 + c] : Wb[k * 32 + (c - 32)];
        else    w = Wa[k * 64 + c];
        WsT[c * 132 + k] = __uint_as_float(f2tf32(w));
    }
    __syncthreads();

    const int lane = tid & 31;
    const int warp = tid >> 5;
    const int g   = lane >> 2;   // 0..7
    const int tig = lane & 3;    // 0..3

    const int row0 = blockIdx.x * 128 + warp * 16 + g;
    const int row1 = row0 + 8;
    const bool v0 = row0 < N;
    const bool v1 = row1 < N;
    const TA* A0 = A + (size_t)(v0 ? row0 : 0) * K;
    const TA* A1 = A + (size_t)(v1 ? row1 : 0) * K;

    float acc[8][4];
    #pragma unroll
    for (int i = 0; i < 8; i++)
        #pragma unroll
        for (int j = 0; j < 4; j++) acc[i][j] = 0.f;

    for (int kc = 0; kc < K; kc += 8) {
        uint32_t a0 = f2tf32(v0 ? (float)__ldg(A0 + kc + tig)     : 0.f);
        uint32_t a1 = f2tf32(v1 ? (float)__ldg(A1 + kc + tig)     : 0.f);
        uint32_t a2 = f2tf32(v0 ? (float)__ldg(A0 + kc + tig + 4) : 0.f);
        uint32_t a3 = f2tf32(v1 ? (float)__ldg(A1 + kc + tig + 4) : 0.f);
        #pragma unroll
        for (int nt = 0; nt < 8; nt++) {
            const float* bp = &WsT[(nt * 8 + g) * 132 + kc + tig];
            uint32_t b0 = __float_as_uint(bp[0]);
            uint32_t b1 = __float_as_uint(bp[4]);
            asm volatile(
                "mma.sync.aligned.m16n8k8.row.col.f32.tf32.tf32.f32 "
                "{%0,%1,%2,%3}, {%4,%5,%6,%7}, {%8,%9}, {%0,%1,%2,%3};"
                : "+f"(acc[nt][0]), "+f"(acc[nt][1]),
                  "+f"(acc[nt][2]), "+f"(acc[nt][3])
                : "r"(a0), "r"(a1), "r"(a2), "r"(a3), "r"(b0), "r"(b1));
        }
    }

    #pragma unroll
    for (int nt = 0; nt < 8; nt++) {
        int cp = nt * 4 + tig;   // half2 column-pair (cols 2cp, 2cp+1)
        if (v0) out[(size_t)row0 * 32 + cp] = __floats2half2_rn(acc[nt][0], acc[nt][1]);
        if (v1) out[(size_t)row1 * 32 + cp] = __floats2half2_rn(acc[nt][2], acc[nt][3]);
    }
}

// ---------------- aggregation over pre-scaled hs (gather, 1 warp/node) --------
// hs[s] = dinv[s]*h[s].  acc = Σ_{s in nbrs(d)} hs[s] + hs[d]  (plain adds,
// no per-edge weight load). col indices read via int4 (1 LDG / 4 edges).
// mode A (out_b==null): write fp16 out_a[d] = dinv[d]*relu(dinv[d]*acc + bias_a)
//   (pre-scaled for next layer).
// mode B: fp32 split: ch0..31 -> out_a (+bias_a), ch32..63 -> out_b (+bias_b),
//   value = dinv[d]*acc + bias.
__global__ void agg_kernel(const __half2* __restrict__ hs,
                           const float* __restrict__ bias_a,
                           const float* __restrict__ bias_b,
                           void* __restrict__ out_a,
                           float* __restrict__ out_b) {
    int warp = (blockIdx.x * blockDim.x + threadIdx.x) >> 5;
    int lane = threadIdx.x & 31;
    if (warp >= N_NODES) return;
    const int d = warp;

    int beg = g_rowptr[d];
    int end = g_rowptr[d + 1];
    float2 acc = make_float2(0.f, 0.f);

    int j = beg;
    // peel to 16B alignment of g_col
    while (j < end && (j & 3)) {
        int s = g_col[j++];
        float2 v = __half22float2(hs[(size_t)s * 32 + lane]);
        acc.x += v.x; acc.y += v.y;
    }
    for (; j + 3 < end; j += 4) {
        int4 c = *(const int4*)&g_col[j];
        float2 v0 = __half22float2(hs[(size_t)c.x * 32 + lane]);
        float2 v1 = __half22float2(hs[(size_t)c.y * 32 + lane]);
        float2 v2 = __half22float2(hs[(size_t)c.z * 32 + lane]);
        float2 v3 = __half22float2(hs[(size_t)c.w * 32 + lane]);
        acc.x += v0.x + v1.x + v2.x + v3.x;
        acc.y += v0.y + v1.y + v2.y + v3.y;
    }
    for (; j < end; j++) {
        int s = g_col[j];
        float2 v = __half22float2(hs[(size_t)s * 32 + lane]);
        acc.x += v.x; acc.y += v.y;
    }

    // self loop (hs already pre-scaled: hs[d] = dinv[d]*h[d])
    {
        float2 v = __half22float2(hs[(size_t)d * 32 + lane]);
        acc.x += v.x; acc.y += v.y;
    }

    float dd = g_dinv[d];
    if (out_b == nullptr) {
        float2 b = ((const float2*)bias_a)[lane];
        float rx = fmaxf(fmaf(dd, acc.x, b.x), 0.f);
        float ry = fmaxf(fmaf(dd, acc.y, b.y), 0.f);
        ((__half2*)out_a)[(size_t)d * 32 + lane] =
            __floats2half2_rn(rx * dd, ry * dd);   // pre-scale for layer 2
    } else {
        if (lane < 16) {
            float2 b = ((const float2*)bias_a)[lane];
            ((float2*)out_a)[(size_t)d * 16 + lane] =
                make_float2(fmaf(dd, acc.x, b.x), fmaf(dd, acc.y, b.y));
        } else {
            float2 b = ((const float2*)bias_b)[lane - 16];
            ((float2*)out_b)[(size_t)d * 16 + (lane - 16)] =
                make_float2(fmaf(dd, acc.x, b.x), fmaf(dd, acc.y, b.y));
        }
    }
}

// ---------------- stream/event context (created at program load) ----------------
namespace {
struct Ctx {
    cudaStream_t s2 = nullptr;
    cudaEvent_t e_fork = nullptr, e_join = nullptr;
    bool ok = false;
    Ctx() {
        ok = (cudaStreamCreateWithFlags(&s2, cudaStreamNonBlocking) == cudaSuccess) &&
             (cudaEventCreateWithFlags(&e_fork, cudaEventDisableTiming) == cudaSuccess) &&
             (cudaEventCreateWithFlags(&e_join, cudaEventDisableTiming) == cudaSuccess);
    }
};
Ctx g_ctx;
}

// ---------------- launch ----------------
extern "C" void kernel_launch(void* const* d_in, const int* in_sizes, int n_in,
                              void* d_out, int out_size) {
    const float* x    = (const float*)d_in[0];
    const void*  ei   = d_in[1];
    const float* W1   = (const float*)d_in[2];
    const float* b1   = (const float*)d_in[3];
    const float* W_mu = (const float*)d_in[4];
    const float* b_mu = (const float*)d_in[5];
    const float* W_ls = (const float*)d_in[6];
    const float* b_ls = (const float*)d_in[7];
    float* out = (float*)d_out;

    const int E = in_sizes[1] / 2;
    const int N = N_NODES;

    __half2* h0;  cudaGetSymbolAddress((void**)&h0, g_h0);
    __half2* h1;  cudaGetSymbolAddress((void**)&h1, g_h1);
    __half2* h2;  cudaGetSymbolAddress((void**)&h2, g_h2);

    const int eb = (E + 255) / 256;
    const int nb512 = (N + 511) / 512;           // 196

    const bool fork = g_ctx.ok;
    cudaStream_t sc = fork ? g_ctx.s2 : (cudaStream_t)0;

    if (fork) {
        cudaEventRecord(g_ctx.e_fork, 0);
        cudaStreamWaitEvent(g_ctx.s2, g_ctx.e_fork, 0);
    }

    // ---- CSR build (side stream, overlaps gemm1) ----
    zero_detect_kernel<<<(N + 255) / 256 + 1, 256, 0, sc>>>((const unsigned int*)ei);
    count_kernel<<<eb, 256, 0, sc>>>(ei, E);
    scan1_kernel<<<nb512, 512, 0, sc>>>();
    finalize_kernel<<<(N + 255) / 256, 256, 0, sc>>>(E, nb512);
    fill_kernel<<<eb, 256, 0, sc>>>(ei, E);
    if (fork) cudaEventRecord(g_ctx.e_join, g_ctx.s2);

    // ---- layer 1 GEMM (default stream, independent of CSR) ----
    gemm_tf32_kernel<float><<<(N + 127) / 128, 256>>>(x, W1, nullptr, h0, N, IN_CH);

    if (fork) cudaStreamWaitEvent((cudaStream_t)0, g_ctx.e_join, 0);

    // ---- pre-scale h0 by dinv (in place), then layer-1 aggregate ----
    scale_h_kernel<<<(N * 32 + 255) / 256, 256>>>(h0);
    agg_kernel<<<(N * 32 + 255) / 256, 256>>>(h0, b1, nullptr, h1, nullptr);

    // ---- layer 2 fused mu|logstd GEMM (input pre-scaled -> output pre-scaled) --
    gemm_tf32_kernel<__half><<<(N + 127) / 128, 256>>>((const __half*)h1, W_mu, W_ls, h2, N, HID);

    // ---- final aggregate, split fp32 writes to d_out ----
    agg_kernel<<<(N * 32 + 255) / 256, 256>>>(h2, b_mu, b_ls,
                                              out, out + (size_t)N * OUTC);
}

// round 8
// speedup vs baseline: 1.2146x; 1.1685x over previous
#include <cuda_runtime.h>
#include <cuda_fp16.h>
#include <cstddef>
#include <cstdint>

// ---------------- problem constants ----------------
#define N_NODES 100000
#define N_EDGES 1600000
#define IN_CH   128
#define HID     64
#define OUTC    32

// ---------------- static device scratch (no allocation allowed) ----------------
__device__ int     g_cnt[N_NODES];
__device__ int     g_rowptr[N_NODES + 1];
__device__ int     g_cursor[N_NODES];
__device__ int     g_bsum[256];
__device__ __align__(16) int g_col[N_EDGES];
__device__ float   g_dinv[N_NODES];
__device__ __align__(16) __half2 g_h0[(size_t)N_NODES * 32]; // x@W1, pre-scaled
__device__ __align__(16) __half2 g_h1[(size_t)N_NODES * 32]; // dinv*relu(agg+b1)
__device__ __align__(16) __half2 g_h2[(size_t)N_NODES * 32]; // h1s@[W_mu|W_ls]
__device__ int     g_is64;

// ---------------- zero counters + dtype detection (fused) --------------------
__global__ void zero_detect_kernel(const unsigned int* __restrict__ words) {
    int i = blockIdx.x * blockDim.x + threadIdx.x;
    if (i < N_NODES) g_cnt[i] = 0;
    if (blockIdx.x == gridDim.x - 1) {
        __shared__ int nz;
        if (threadIdx.x == 0) nz = 0;
        __syncthreads();
        for (int t = threadIdx.x; t < 4096; t += blockDim.x)
            if (words[2 * t + 1] != 0u) nz = 1;   // benign race
        __syncthreads();
        if (threadIdx.x == 0) g_is64 = nz ? 0 : 1;
    }
}

// ---------------- count in-degree (dst), 1 edge per thread -------------------
__global__ void count_kernel(const void* __restrict__ ei, int E) {
    int e = blockIdx.x * blockDim.x + threadIdx.x;
    if (e >= E) return;
    int d;
    if (g_is64) d = (int)((const long long*)ei)[E + e];
    else        d = ((const int*)ei)[E + e];
    atomicAdd(&g_cnt[d], 1);
}

// ---------------- scan stage 1: per-512-block exclusive scan ----------------
__global__ void scan1_kernel() {
    __shared__ int sh[512];
    int tid = threadIdx.x;
    int gid = blockIdx.x * 512 + tid;
    int v = (gid < N_NODES) ? g_cnt[gid] : 0;
    sh[tid] = v;
    __syncthreads();
    #pragma unroll
    for (int off = 1; off < 512; off <<= 1) {
        int t = (tid >= off) ? sh[tid - off] : 0;
        __syncthreads();
        sh[tid] += t;
        __syncthreads();
    }
    if (gid < N_NODES) g_rowptr[gid] = sh[tid] - v;
    if (tid == 511) g_bsum[blockIdx.x] = sh[511];
}

// ------- finalize (fused scan2): each block re-scans bsum in smem ------------
__global__ void finalize_kernel(int E, int nb) {
    __shared__ int sh[256];
    __shared__ int ex[256];
    int tid = threadIdx.x;
    int v = (tid < nb) ? g_bsum[tid] : 0;
    sh[tid] = v;
    __syncthreads();
    #pragma unroll
    for (int off = 1; off < 256; off <<= 1) {
        int t = (tid >= off) ? sh[tid - off] : 0;
        __syncthreads();
        sh[tid] += t;
        __syncthreads();
    }
    ex[tid] = sh[tid] - v;
    __syncthreads();

    int i = blockIdx.x * 256 + tid;
    if (i < N_NODES) {
        int r = g_rowptr[i] + ex[i >> 9];
        g_rowptr[i] = r;
        g_cursor[i] = r;
        g_dinv[i] = rsqrtf((float)(g_cnt[i] + 1));  // +1 self loop
    }
    if (i == 0) g_rowptr[N_NODES] = E;
}

// ---------------- fill CSR column indices, 1 edge per thread ----------------
__global__ void fill_kernel(const void* __restrict__ ei, int E) {
    int e = blockIdx.x * blockDim.x + threadIdx.x;
    if (e >= E) return;
    int s, d;
    if (g_is64) {
        s = (int)((const long long*)ei)[e];
        d = (int)((const long long*)ei)[E + e];
    } else {
        s = ((const int*)ei)[e];
        d = ((const int*)ei)[E + e];
    }
    int pos = atomicAdd(&g_cursor[d], 1);
    g_col[pos] = s;
}

// ------- in-place pre-scale: h[i] *= dinv[node(i)] (node = i>>5) -------------
__global__ void scale_h_kernel(__half2* __restrict__ h) {
    int i = blockIdx.x * blockDim.x + threadIdx.x;
    if (i >= N_NODES * 32) return;
    float dd = g_dinv[i >> 5];
    float2 v = __half22float2(h[i]);
    h[i] = __floats2half2_rn(v.x * dd, v.y * dd);
}

// ---------------- tf32 helper ----------------
__device__ __forceinline__ uint32_t f2tf32(float x) {
    uint32_t r;
    asm("cvt.rna.tf32.f32 %0, %1;" : "=r"(r) : "f"(x));
    return r;
}

// ---------------- TF32 tensor-core GEMM: out[N,64] = A[N,K] @ W[K,64] ----------
template <typename TA>
__global__ __launch_bounds__(256) void gemm_tf32_kernel(
        const TA* __restrict__ A,
        const float* __restrict__ Wa,
        const float* __restrict__ Wb,
        __half2* __restrict__ out,
        int N, int K) {
    __shared__ float WsT[64 * 132];
    const int tid = threadIdx.x;

    for (int e = tid; e < 64 * K; e += 256) {
        int c = e & 63;
        int k = e >> 6;
        float w;
        if (Wb) w = (c < 32) ? Wa[k * 32 + c] : Wb[k * 32 + (c - 32)];
        else    w = Wa[k * 64 + c];
        WsT[c * 132 + k] = __uint_as_float(f2tf32(w));
    }
    __syncthreads();

    const int lane = tid & 31;
    const int warp = tid >> 5;
    const int g   = lane >> 2;
    const int tig = lane & 3;

    const int row0 = blockIdx.x * 128 + warp * 16 + g;
    const int row1 = row0 + 8;
    const bool v0 = row0 < N;
    const bool v1 = row1 < N;
    const TA* A0 = A + (size_t)(v0 ? row0 : 0) * K;
    const TA* A1 = A + (size_t)(v1 ? row1 : 0) * K;

    float acc[8][4];
    #pragma unroll
    for (int i = 0; i < 8; i++)
        #pragma unroll
        for (int j = 0; j < 4; j++) acc[i][j] = 0.f;

    for (int kc = 0; kc < K; kc += 8) {
        uint32_t a0 = f2tf32(v0 ? (float)__ldg(A0 + kc + tig)     : 0.f);
        uint32_t a1 = f2tf32(v1 ? (float)__ldg(A1 + kc + tig)     : 0.f);
        uint32_t a2 = f2tf32(v0 ? (float)__ldg(A0 + kc + tig + 4) : 0.f);
        uint32_t a3 = f2tf32(v1 ? (float)__ldg(A1 + kc + tig + 4) : 0.f);
        #pragma unroll
        for (int nt = 0; nt < 8; nt++) {
            const float* bp = &WsT[(nt * 8 + g) * 132 + kc + tig];
            uint32_t b0 = __float_as_uint(bp[0]);
            uint32_t b1 = __float_as_uint(bp[4]);
            asm volatile(
                "mma.sync.aligned.m16n8k8.row.col.f32.tf32.tf32.f32 "
                "{%0,%1,%2,%3}, {%4,%5,%6,%7}, {%8,%9}, {%0,%1,%2,%3};"
                : "+f"(acc[nt][0]), "+f"(acc[nt][1]),
                  "+f"(acc[nt][2]), "+f"(acc[nt][3])
                : "r"(a0), "r"(a1), "r"(a2), "r"(a3), "r"(b0), "r"(b1));
        }
    }

    #pragma unroll
    for (int nt = 0; nt < 8; nt++) {
        int cp = nt * 4 + tig;
        if (v0) out[(size_t)row0 * 32 + cp] = __floats2half2_rn(acc[nt][0], acc[nt][1]);
        if (v1) out[(size_t)row1 * 32 + cp] = __floats2half2_rn(acc[nt][2], acc[nt][3]);
    }
}

// -------- aggregation v2: 4 nodes per warp, 8 lanes per 128B row -------------
// Subgroup q = lanes [8q, 8q+8) handles node d = 4*warp + q.
// Each lane holds 8 channels (uint4 = 4 half2). One LDG.128 per subgroup-edge:
// a warp-level gather instruction fetches 4 independent source rows at once.
// acc = sum of pre-scaled hs rows over nbrs(d) + hs[d] (self loop).
// mode A (out_b==null): out_a[d] = fp16( dinv[d] * relu(dinv[d]*acc + bias_a) )
// mode B: fp32 split: global ch 0..31 (+bias_a) -> out_a; 32..63 (+bias_b) -> out_b.
__global__ __launch_bounds__(256) void agg_kernel(
        const __half2* __restrict__ hs,
        const float* __restrict__ bias_a,
        const float* __restrict__ bias_b,
        void* __restrict__ out_a,
        float* __restrict__ out_b) {
    const int warp = (blockIdx.x * blockDim.x + threadIdx.x) >> 5;
    const int lane = threadIdx.x & 31;
    const int q = lane >> 3;         // subgroup 0..3
    const int t = lane & 7;          // lane within subgroup
    const int d = warp * 4 + q;      // node (grid sized so d < N_NODES always)
    if (d >= N_NODES) return;

    const uint4* __restrict__ rows = (const uint4*)hs;   // row s: rows[s*8 + t]

    const int beg = g_rowptr[d];
    const int end = g_rowptr[d + 1];

    float2 a0 = make_float2(0.f, 0.f);
    float2 a1 = make_float2(0.f, 0.f);
    float2 a2 = make_float2(0.f, 0.f);
    float2 a3 = make_float2(0.f, 0.f);

    #define ACC_U4(v) do {                                           \
        float2 u;                                                    \
        u = __half22float2(*(const __half2*)&(v).x); a0.x += u.x; a0.y += u.y; \
        u = __half22float2(*(const __half2*)&(v).y); a1.x += u.x; a1.y += u.y; \
        u = __half22float2(*(const __half2*)&(v).z); a2.x += u.x; a2.y += u.y; \
        u = __half22float2(*(const __half2*)&(v).w); a3.x += u.x; a3.y += u.y; \
    } while (0)

    int j = beg;
    for (; j + 1 < end; j += 2) {
        int s0 = g_col[j];
        int s1 = g_col[j + 1];
        uint4 v0 = rows[(size_t)s0 * 8 + t];
        uint4 v1 = rows[(size_t)s1 * 8 + t];
        ACC_U4(v0);
        ACC_U4(v1);
    }
    if (j < end) {
        int s0 = g_col[j];
        uint4 v0 = rows[(size_t)s0 * 8 + t];
        ACC_U4(v0);
    }
    {   // self loop (hs pre-scaled)
        uint4 v = rows[(size_t)d * 8 + t];
        ACC_U4(v);
    }
    #undef ACC_U4

    const float dd = g_dinv[d];

    if (out_b == nullptr) {
        // bias for channels 8t..8t+7 -> float2 indices 4t..4t+3
        const float2* bp = (const float2*)bias_a + 4 * t;
        float2 b0 = bp[0], b1 = bp[1], b2 = bp[2], b3 = bp[3];
        float r0x = fmaxf(fmaf(dd, a0.x, b0.x), 0.f) * dd;
        float r0y = fmaxf(fmaf(dd, a0.y, b0.y), 0.f) * dd;
        float r1x = fmaxf(fmaf(dd, a1.x, b1.x), 0.f) * dd;
        float r1y = fmaxf(fmaf(dd, a1.y, b1.y), 0.f) * dd;
        float r2x = fmaxf(fmaf(dd, a2.x, b2.x), 0.f) * dd;
        float r2y = fmaxf(fmaf(dd, a2.y, b2.y), 0.f) * dd;
        float r3x = fmaxf(fmaf(dd, a3.x, b3.x), 0.f) * dd;
        float r3y = fmaxf(fmaf(dd, a3.y, b3.y), 0.f) * dd;
        uint4 o;
        *(__half2*)&o.x = __floats2half2_rn(r0x, r0y);
        *(__half2*)&o.y = __floats2half2_rn(r1x, r1y);
        *(__half2*)&o.z = __floats2half2_rn(r2x, r2y);
        *(__half2*)&o.w = __floats2half2_rn(r3x, r3y);
        ((uint4*)out_a)[(size_t)d * 8 + t] = o;
    } else {
        // fp32 split: lane covers global channels 8t..8t+7
        float v[8] = { a0.x, a0.y, a1.x, a1.y, a2.x, a2.y, a3.x, a3.y };
        if (t < 4) {
            const float4* bp = (const float4*)bias_a + 2 * t;   // ch 8t..8t+7
            float4 b0 = bp[0], b1 = bp[1];
            float4 w0 = make_float4(fmaf(dd, v[0], b0.x), fmaf(dd, v[1], b0.y),
                                    fmaf(dd, v[2], b0.z), fmaf(dd, v[3], b0.w));
            float4 w1 = make_float4(fmaf(dd, v[4], b1.x), fmaf(dd, v[5], b1.y),
                                    fmaf(dd, v[6], b1.z), fmaf(dd, v[7], b1.w));
            float* o = (float*)out_a + (size_t)d * 32 + 8 * t;
            *(float4*)o = w0;
            *(float4*)(o + 4) = w1;
        } else {
            int tt = t - 4;                                    // local ch 8tt..
            const float4* bp = (const float4*)bias_b + 2 * tt;
            float4 b0 = bp[0], b1 = bp[1];
            float4 w0 = make_float4(fmaf(dd, v[0], b0.x), fmaf(dd, v[1], b0.y),
                                    fmaf(dd, v[2], b0.z), fmaf(dd, v[3], b0.w));
            float4 w1 = make_float4(fmaf(dd, v[4], b1.x), fmaf(dd, v[5], b1.y),
                                    fmaf(dd, v[6], b1.z), fmaf(dd, v[7], b1.w));
            float* o = out_b + (size_t)d * 32 + 8 * tt;
            *(float4*)o = w0;
            *(float4*)(o + 4) = w1;
        }
    }
}

// ---------------- stream/event context (created at program load) ----------------
namespace {
struct Ctx {
    cudaStream_t s2 = nullptr;
    cudaEvent_t e_fork = nullptr, e_join = nullptr;
    bool ok = false;
    Ctx() {
        ok = (cudaStreamCreateWithFlags(&s2, cudaStreamNonBlocking) == cudaSuccess) &&
             (cudaEventCreateWithFlags(&e_fork, cudaEventDisableTiming) == cudaSuccess) &&
             (cudaEventCreateWithFlags(&e_join, cudaEventDisableTiming) == cudaSuccess);
    }
};
Ctx g_ctx;
}

// ---------------- launch ----------------
extern "C" void kernel_launch(void* const* d_in, const int* in_sizes, int n_in,
                              void* d_out, int out_size) {
    const float* x    = (const float*)d_in[0];
    const void*  ei   = d_in[1];
    const float* W1   = (const float*)d_in[2];
    const float* b1   = (const float*)d_in[3];
    const float* W_mu = (const float*)d_in[4];
    const float* b_mu = (const float*)d_in[5];
    const float* W_ls = (const float*)d_in[6];
    const float* b_ls = (const float*)d_in[7];
    float* out = (float*)d_out;

    const int E = in_sizes[1] / 2;
    const int N = N_NODES;

    __half2* h0;  cudaGetSymbolAddress((void**)&h0, g_h0);
    __half2* h1;  cudaGetSymbolAddress((void**)&h1, g_h1);
    __half2* h2;  cudaGetSymbolAddress((void**)&h2, g_h2);

    const int eb = (E + 255) / 256;
    const int nb512 = (N + 511) / 512;

    // agg v2: 4 nodes/warp -> 25000 warps -> 3125 blocks of 256
    const int agg_blocks = ((N + 3) / 4 * 32 + 255) / 256;

    const bool fork = g_ctx.ok;
    cudaStream_t sc = fork ? g_ctx.s2 : (cudaStream_t)0;

    if (fork) {
        cudaEventRecord(g_ctx.e_fork, 0);
        cudaStreamWaitEvent(g_ctx.s2, g_ctx.e_fork, 0);
    }

    // ---- CSR build (side stream, overlaps gemm1) ----
    zero_detect_kernel<<<(N + 255) / 256 + 1, 256, 0, sc>>>((const unsigned int*)ei);
    count_kernel<<<eb, 256, 0, sc>>>(ei, E);
    scan1_kernel<<<nb512, 512, 0, sc>>>();
    finalize_kernel<<<(N + 255) / 256, 256, 0, sc>>>(E, nb512);
    fill_kernel<<<eb, 256, 0, sc>>>(ei, E);
    if (fork) cudaEventRecord(g_ctx.e_join, g_ctx.s2);

    // ---- layer 1 GEMM (default stream, independent of CSR) ----
    gemm_tf32_kernel<float><<<(N + 127) / 128, 256>>>(x, W1, nullptr, h0, N, IN_CH);

    if (fork) cudaStreamWaitEvent((cudaStream_t)0, g_ctx.e_join, 0);

    // ---- pre-scale h0 by dinv (in place), then layer-1 aggregate ----
    scale_h_kernel<<<(N * 32 + 255) / 256, 256>>>(h0);
    agg_kernel<<<agg_blocks, 256>>>(h0, b1, nullptr, h1, nullptr);

    // ---- layer 2 fused mu|logstd GEMM (pre-scaled in -> pre-scaled out) ----
    gemm_tf32_kernel<__half><<<(N + 127) / 128, 256>>>((const __half*)h1, W_mu, W_ls, h2, N, HID);

    // ---- final aggregate, split fp32 writes to d_out ----
    agg_kernel<<<agg_blocks, 256>>>(h2, b_mu, b_ls,
                                    out, out + (size_t)N * OUTC);
}

// round 9
// speedup vs baseline: 1.2954x; 1.0665x over previous
#include <cuda_runtime.h>
#include <cuda_fp16.h>
#include <cstddef>
#include <cstdint>

// ---------------- problem constants ----------------
#define N_NODES 100000
#define N_EDGES 1600000
#define IN_CH   128
#define HID     64
#define OUTC    32

// ---------------- static device scratch (no allocation allowed) ----------------
// g_cnt / g_total are zero at load (static init) and re-zeroed by cleanup_kernel
// at the end of every invocation (overlapped, off the critical path).
__device__ int     g_cnt[N_NODES];
__device__ int     g_total;
__device__ int     g_rowbeg[N_NODES];
__device__ int     g_rowend[N_NODES];
__device__ int     g_cursor[N_NODES];
__device__ __align__(16) int g_col[N_EDGES];
__device__ float   g_dinv[N_NODES];
__device__ __align__(16) __half2 g_h0[(size_t)N_NODES * 32]; // x@W1 -> pre-scaled
__device__ __align__(16) __half2 g_h1[(size_t)N_NODES * 32]; // dinv*relu(agg+b1)
__device__ __align__(16) __half2 g_h2[(size_t)N_NODES * 32]; // h1s@[W_mu|W_ls]
__device__ int     g_is64;

// ---------------- dtype detection: int64 vs int32 edge_index -----------------
// int64 little-endian with node ids < 2^31 -> every high 32-bit word is zero.
__global__ void detect_kernel(const unsigned int* __restrict__ words) {
    __shared__ int nz;
    if (threadIdx.x == 0) nz = 0;
    __syncthreads();
    for (int t = threadIdx.x; t < 4096; t += blockDim.x)
        if (words[2 * t + 1] != 0u) nz = 1;   // benign race
    __syncthreads();
    if (threadIdx.x == 0) g_is64 = nz ? 0 : 1;
}

// ---------------- count in-degree (dst), 1 edge per thread -------------------
__global__ void count_kernel(const void* __restrict__ ei, int E) {
    int e = blockIdx.x * blockDim.x + threadIdx.x;
    if (e >= E) return;
    int d;
    if (g_is64) d = (int)((const long long*)ei)[E + e];
    else        d = ((const int*)ei)[E + e];
    atomicAdd(&g_cnt[d], 1);
}

// -------- alloc: unordered CSR range assignment (replaces scan+finalize) -----
// Block-local inclusive scan of counts; ONE atomicAdd per block grabs a base
// range from g_total. Row ranges are disjoint+contiguous; global order is
// irrelevant for gather aggregation.
__global__ void alloc_kernel() {
    __shared__ int sh[512];
    __shared__ int base;
    int tid = threadIdx.x;
    int gid = blockIdx.x * 512 + tid;
    int v = (gid < N_NODES) ? g_cnt[gid] : 0;
    sh[tid] = v;
    __syncthreads();
    #pragma unroll
    for (int off = 1; off < 512; off <<= 1) {
        int t = (tid >= off) ? sh[tid - off] : 0;
        __syncthreads();
        sh[tid] += t;
        __syncthreads();
    }
    if (tid == 511) base = atomicAdd(&g_total, sh[511]);
    __syncthreads();
    if (gid < N_NODES) {
        int r = base + sh[tid] - v;   // exclusive offset within block + base
        g_rowbeg[gid]  = r;
        g_cursor[gid]  = r;
        g_rowend[gid]  = r + v;
        g_dinv[gid] = rsqrtf((float)(v + 1));  // +1 self loop
    }
}

// ------- fused fill (edge-parallel) + pre-scale h0 (element-parallel) --------
// Grid covers N_NODES*32 half2 elements; threads < E also place one edge.
__global__ void fill_scale_kernel(const void* __restrict__ ei, int E,
                                  __half2* __restrict__ h) {
    int i = blockIdx.x * blockDim.x + threadIdx.x;

    if (i < N_NODES * 32) {
        float dd = g_dinv[i >> 5];
        float2 v = __half22float2(h[i]);
        h[i] = __floats2half2_rn(v.x * dd, v.y * dd);
    }

    if (i < E) {
        int s, d;
        if (g_is64) {
            s = (int)((const long long*)ei)[i];
            d = (int)((const long long*)ei)[E + i];
        } else {
            s = ((const int*)ei)[i];
            d = ((const int*)ei)[E + i];
        }
        int pos = atomicAdd(&g_cursor[d], 1);
        g_col[pos] = s;
    }
}

// ------- cleanup: re-zero counters for the next invocation (overlapped) ------
__global__ void cleanup_kernel() {
    int i = blockIdx.x * blockDim.x + threadIdx.x;
    if (i < N_NODES) g_cnt[i] = 0;
    if (i == 0) g_total = 0;
}

// ---------------- tf32 helper ----------------
__device__ __forceinline__ uint32_t f2tf32(float x) {
    uint32_t r;
    asm("cvt.rna.tf32.f32 %0, %1;" : "=r"(r) : "f"(x));
    return r;
}

// ---------------- TF32 tensor-core GEMM: out[N,64] = A[N,K] @ W[K,64] ----------
template <typename TA>
__global__ __launch_bounds__(256) void gemm_tf32_kernel(
        const TA* __restrict__ A,
        const float* __restrict__ Wa,
        const float* __restrict__ Wb,
        __half2* __restrict__ out,
        int N, int K) {
    __shared__ float WsT[64 * 132];
    const int tid = threadIdx.x;

    for (int e = tid; e < 64 * K; e += 256) {
        int c = e & 63;
        int k = e >> 6;
        float w;
        if (Wb) w = (c < 32) ? Wa[k * 32 + c] : Wb[k * 32 + (c - 32)];
        else    w = Wa[k * 64 + c];
        WsT[c * 132 + k] = __uint_as_float(f2tf32(w));
    }
    __syncthreads();

    const int lane = tid & 31;
    const int warp = tid >> 5;
    const int g   = lane >> 2;
    const int tig = lane & 3;

    const int row0 = blockIdx.x * 128 + warp * 16 + g;
    const int row1 = row0 + 8;
    const bool v0 = row0 < N;
    const bool v1 = row1 < N;
    const TA* A0 = A + (size_t)(v0 ? row0 : 0) * K;
    const TA* A1 = A + (size_t)(v1 ? row1 : 0) * K;

    float acc[8][4];
    #pragma unroll
    for (int i = 0; i < 8; i++)
        #pragma unroll
        for (int j = 0; j < 4; j++) acc[i][j] = 0.f;

    for (int kc = 0; kc < K; kc += 8) {
        uint32_t a0 = f2tf32(v0 ? (float)__ldg(A0 + kc + tig)     : 0.f);
        uint32_t a1 = f2tf32(v1 ? (float)__ldg(A1 + kc + tig)     : 0.f);
        uint32_t a2 = f2tf32(v0 ? (float)__ldg(A0 + kc + tig + 4) : 0.f);
        uint32_t a3 = f2tf32(v1 ? (float)__ldg(A1 + kc + tig + 4) : 0.f);
        #pragma unroll
        for (int nt = 0; nt < 8; nt++) {
            const float* bp = &WsT[(nt * 8 + g) * 132 + kc + tig];
            uint32_t b0 = __float_as_uint(bp[0]);
            uint32_t b1 = __float_as_uint(bp[4]);
            asm volatile(
                "mma.sync.aligned.m16n8k8.row.col.f32.tf32.tf32.f32 "
                "{%0,%1,%2,%3}, {%4,%5,%6,%7}, {%8,%9}, {%0,%1,%2,%3};"
                : "+f"(acc[nt][0]), "+f"(acc[nt][1]),
                  "+f"(acc[nt][2]), "+f"(acc[nt][3])
                : "r"(a0), "r"(a1), "r"(a2), "r"(a3), "r"(b0), "r"(b1));
        }
    }

    #pragma unroll
    for (int nt = 0; nt < 8; nt++) {
        int cp = nt * 4 + tig;
        if (v0) out[(size_t)row0 * 32 + cp] = __floats2half2_rn(acc[nt][0], acc[nt][1]);
        if (v1) out[(size_t)row1 * 32 + cp] = __floats2half2_rn(acc[nt][2], acc[nt][3]);
    }
}

// -------- aggregation: 4 nodes per warp, 8 lanes per 128B row, 4-edge unroll --
// Subgroup q = lanes [8q,8q+8) handles node d = 4*warp + q; lane holds 8 ch.
// acc = sum of pre-scaled hs rows over nbrs(d) + hs[d].
// mode A (out_b==null): out_a[d] = fp16( dinv[d]*relu(dinv[d]*acc + bias_a) )
// mode B: fp32 split: ch 0..31 (+bias_a) -> out_a; 32..63 (+bias_b) -> out_b.
__global__ __launch_bounds__(256) void agg_kernel(
        const __half2* __restrict__ hs,
        const float* __restrict__ bias_a,
        const float* __restrict__ bias_b,
        void* __restrict__ out_a,
        float* __restrict__ out_b) {
    const int warp = (blockIdx.x * blockDim.x + threadIdx.x) >> 5;
    const int lane = threadIdx.x & 31;
    const int q = lane >> 3;
    const int t = lane & 7;
    const int d = warp * 4 + q;
    if (d >= N_NODES) return;

    const uint4* __restrict__ rows = (const uint4*)hs;

    const int beg = g_rowbeg[d];
    const int end = g_rowend[d];

    float2 a0 = make_float2(0.f, 0.f);
    float2 a1 = make_float2(0.f, 0.f);
    float2 a2 = make_float2(0.f, 0.f);
    float2 a3 = make_float2(0.f, 0.f);

    #define ACC_U4(v) do {                                           \
        float2 u;                                                    \
        u = __half22float2(*(const __half2*)&(v).x); a0.x += u.x; a0.y += u.y; \
        u = __half22float2(*(const __half2*)&(v).y); a1.x += u.x; a1.y += u.y; \
        u = __half22float2(*(const __half2*)&(v).z); a2.x += u.x; a2.y += u.y; \
        u = __half22float2(*(const __half2*)&(v).w); a3.x += u.x; a3.y += u.y; \
    } while (0)

    int j = beg;
    for (; j + 3 < end; j += 4) {
        int s0 = g_col[j];
        int s1 = g_col[j + 1];
        int s2 = g_col[j + 2];
        int s3 = g_col[j + 3];
        uint4 v0 = rows[(size_t)s0 * 8 + t];
        uint4 v1 = rows[(size_t)s1 * 8 + t];
        uint4 v2 = rows[(size_t)s2 * 8 + t];
        uint4 v3 = rows[(size_t)s3 * 8 + t];
        ACC_U4(v0); ACC_U4(v1); ACC_U4(v2); ACC_U4(v3);
    }
    for (; j < end; j++) {
        int s0 = g_col[j];
        uint4 v0 = rows[(size_t)s0 * 8 + t];
        ACC_U4(v0);
    }
    {   // self loop (hs pre-scaled)
        uint4 v = rows[(size_t)d * 8 + t];
        ACC_U4(v);
    }
    #undef ACC_U4

    const float dd = g_dinv[d];

    if (out_b == nullptr) {
        const float2* bp = (const float2*)bias_a + 4 * t;
        float2 b0 = bp[0], b1 = bp[1], b2 = bp[2], b3 = bp[3];
        float r0x = fmaxf(fmaf(dd, a0.x, b0.x), 0.f) * dd;
        float r0y = fmaxf(fmaf(dd, a0.y, b0.y), 0.f) * dd;
        float r1x = fmaxf(fmaf(dd, a1.x, b1.x), 0.f) * dd;
        float r1y = fmaxf(fmaf(dd, a1.y, b1.y), 0.f) * dd;
        float r2x = fmaxf(fmaf(dd, a2.x, b2.x), 0.f) * dd;
        float r2y = fmaxf(fmaf(dd, a2.y, b2.y), 0.f) * dd;
        float r3x = fmaxf(fmaf(dd, a3.x, b3.x), 0.f) * dd;
        float r3y = fmaxf(fmaf(dd, a3.y, b3.y), 0.f) * dd;
        uint4 o;
        *(__half2*)&o.x = __floats2half2_rn(r0x, r0y);
        *(__half2*)&o.y = __floats2half2_rn(r1x, r1y);
        *(__half2*)&o.z = __floats2half2_rn(r2x, r2y);
        *(__half2*)&o.w = __floats2half2_rn(r3x, r3y);
        ((uint4*)out_a)[(size_t)d * 8 + t] = o;
    } else {
        float v[8] = { a0.x, a0.y, a1.x, a1.y, a2.x, a2.y, a3.x, a3.y };
        if (t < 4) {
            const float4* bp = (const float4*)bias_a + 2 * t;
            float4 b0 = bp[0], b1 = bp[1];
            float4 w0 = make_float4(fmaf(dd, v[0], b0.x), fmaf(dd, v[1], b0.y),
                                    fmaf(dd, v[2], b0.z), fmaf(dd, v[3], b0.w));
            float4 w1 = make_float4(fmaf(dd, v[4], b1.x), fmaf(dd, v[5], b1.y),
                                    fmaf(dd, v[6], b1.z), fmaf(dd, v[7], b1.w));
            float* o = (float*)out_a + (size_t)d * 32 + 8 * t;
            *(float4*)o = w0;
            *(float4*)(o + 4) = w1;
        } else {
            int tt = t - 4;
            const float4* bp = (const float4*)bias_b + 2 * tt;
            float4 b0 = bp[0], b1 = bp[1];
            float4 w0 = make_float4(fmaf(dd, v[0], b0.x), fmaf(dd, v[1], b0.y),
                                    fmaf(dd, v[2], b0.z), fmaf(dd, v[3], b0.w));
            float4 w1 = make_float4(fmaf(dd, v[4], b1.x), fmaf(dd, v[5], b1.y),
                                    fmaf(dd, v[6], b1.z), fmaf(dd, v[7], b1.w));
            float* o = out_b + (size_t)d * 32 + 8 * tt;
            *(float4*)o = w0;
            *(float4*)(o + 4) = w1;
        }
    }
}

// ---------------- stream/event context (created at program load) ----------------
namespace {
struct Ctx {
    cudaStream_t s2 = nullptr;
    cudaEvent_t e_fork = nullptr, e_g1 = nullptr, e_alloc = nullptr, e_cl = nullptr;
    bool ok = false;
    Ctx() {
        ok = (cudaStreamCreateWithFlags(&s2, cudaStreamNonBlocking) == cudaSuccess) &&
             (cudaEventCreateWithFlags(&e_fork, cudaEventDisableTiming) == cudaSuccess) &&
             (cudaEventCreateWithFlags(&e_g1,   cudaEventDisableTiming) == cudaSuccess) &&
             (cudaEventCreateWithFlags(&e_alloc,cudaEventDisableTiming) == cudaSuccess) &&
             (cudaEventCreateWithFlags(&e_cl,   cudaEventDisableTiming) == cudaSuccess);
    }
};
Ctx g_ctx;
}

// ---------------- launch ----------------
extern "C" void kernel_launch(void* const* d_in, const int* in_sizes, int n_in,
                              void* d_out, int out_size) {
    const float* x    = (const float*)d_in[0];
    const void*  ei   = d_in[1];
    const float* W1   = (const float*)d_in[2];
    const float* b1   = (const float*)d_in[3];
    const float* W_mu = (const float*)d_in[4];
    const float* b_mu = (const float*)d_in[5];
    const float* W_ls = (const float*)d_in[6];
    const float* b_ls = (const float*)d_in[7];
    float* out = (float*)d_out;

    const int E = in_sizes[1] / 2;
    const int N = N_NODES;

    __half2* h0;  cudaGetSymbolAddress((void**)&h0, g_h0);
    __half2* h1;  cudaGetSymbolAddress((void**)&h1, g_h1);
    __half2* h2;  cudaGetSymbolAddress((void**)&h2, g_h2);

    const int eb = (E + 255) / 256;
    const int nb512 = (N + 511) / 512;                     // 196
    const int fs_blocks = (N * 32 + 255) / 256;            // covers scale + fill
    const int agg_blocks = ((N + 3) / 4 * 32 + 255) / 256; // 4 nodes/warp

    const bool fork = g_ctx.ok;

    if (fork) {
        cudaEventRecord(g_ctx.e_fork, 0);
        cudaStreamWaitEvent(g_ctx.s2, g_ctx.e_fork, 0);
        // side stream: layer-1 GEMM, fully independent of CSR chain
        gemm_tf32_kernel<float><<<(N + 127) / 128, 256, 0, g_ctx.s2>>>(
            x, W1, nullptr, h0, N, IN_CH);
        cudaEventRecord(g_ctx.e_g1, g_ctx.s2);
    }

    // ---- default stream: CSR chain (g_cnt/g_total arrive pre-zeroed) ----
    detect_kernel<<<1, 256>>>((const unsigned int*)ei);
    count_kernel<<<eb, 256>>>(ei, E);
    alloc_kernel<<<nb512, 512>>>();

    if (fork) {
        cudaEventRecord(g_ctx.e_alloc, 0);
        // side stream: re-zero counters for next run (after alloc consumed them)
        cudaStreamWaitEvent(g_ctx.s2, g_ctx.e_alloc, 0);
        cleanup_kernel<<<(N + 255) / 256, 256, 0, g_ctx.s2>>>();
        cudaEventRecord(g_ctx.e_cl, g_ctx.s2);
        // fill+scale needs h0 (gemm1) and dinv/cursor (alloc)
        cudaStreamWaitEvent((cudaStream_t)0, g_ctx.e_g1, 0);
    } else {
        gemm_tf32_kernel<float><<<(N + 127) / 128, 256>>>(x, W1, nullptr, h0, N, IN_CH);
    }

    // ---- fused: fill CSR columns + pre-scale h0 by dinv ----
    fill_scale_kernel<<<fs_blocks, 256>>>(ei, E, h0);

    // ---- layer 1 aggregate (+bias+relu), fp16 pre-scaled out ----
    agg_kernel<<<agg_blocks, 256>>>(h0, b1, nullptr, h1, nullptr);

    // ---- layer 2 fused mu|logstd GEMM (pre-scaled in -> pre-scaled out) ----
    gemm_tf32_kernel<__half><<<(N + 127) / 128, 256>>>((const __half*)h1, W_mu, W_ls, h2, N, HID);

    // ---- final aggregate, split fp32 writes to d_out ----
    agg_kernel<<<agg_blocks, 256>>>(h2, b_mu, b_ls,
                                    out, out + (size_t)N * OUTC);

    if (fork) {
        cudaStreamWaitEvent((cudaStream_t)0, g_ctx.e_cl, 0);
    } else {
        cleanup_kernel<<<(N + 255) / 256, 256>>>();
    }
}